// round 7
// baseline (speedup 1.0000x reference)
#include <cuda_runtime.h>
#include <cstdint>

#define N_  128
#define C_  64
#define T_  288
#define V_  16
#define S_  3
#define IC_ 16

// tiny scratch: attention matrices after softmax + A  [N, S, V, V]
__device__ float g_att[N_ * S_ * V_ * V_];

// ---- packed f32x2 helpers ------------------------------------------------
__device__ __forceinline__ unsigned long long pk2(float lo, float hi) {
    unsigned long long r;
    asm("mov.b64 %0, {%1, %2};" : "=l"(r) : "f"(lo), "f"(hi));
    return r;
}
__device__ __forceinline__ void ffma2(unsigned long long& acc,
                                      unsigned long long a,
                                      unsigned long long b) {
    asm("fma.rn.f32x2 %0, %1, %2, %0;" : "+l"(acc) : "l"(a), "l"(b));
}
__device__ __forceinline__ float2 upk(unsigned long long p) {
    float2 f;
    asm("mov.b64 {%0, %1}, %2;" : "=f"(f.x), "=f"(f.y) : "l"(p));
    return f;
}
__device__ __forceinline__ uint32_t f2tf32(float f) {
    uint32_t r;
    asm("cvt.rna.tf32.f32 %0, %1;" : "=r"(r) : "f"(f));
    return r;
}
__device__ __forceinline__ void mma_tf32(float& d0, float& d1, float& d2, float& d3,
                                         uint32_t a0, uint32_t a1, uint32_t a2, uint32_t a3,
                                         uint32_t b0, uint32_t b1) {
    asm volatile("mma.sync.aligned.m16n8k8.row.col.f32.tf32.tf32.f32 "
                 "{%0,%1,%2,%3}, {%4,%5,%6,%7}, {%8,%9}, {%0,%1,%2,%3};"
                 : "+f"(d0), "+f"(d1), "+f"(d2), "+f"(d3)
                 : "r"(a0), "r"(a1), "r"(a2), "r"(a3), "r"(b0), "r"(b1));
}

// ---------------------------------------------------------------------------
// Kernel A: unchanged from R6 (passing, 309us)
// ---------------------------------------------------------------------------
__global__ __launch_bounds__(256, 2) void attn_kernel(
    const float* __restrict__ x, const float* __restrict__ A_base,
    const float* __restrict__ PA, const float* __restrict__ Wa,
    const float* __restrict__ ba, const float* __restrict__ Wb,
    const float* __restrict__ bb)
{
    extern __shared__ float smemf[];
    float* sWaT = smemf;               // [64][16]
    float* sWbT = sWaT + 1024;         // [64][16]
    float* sX   = sWbT + 1024;         // [64][256]
    float* sfa  = sX + 16384;          // [16][256]
    float* sfb  = sfa + 4096;          // [16][256]

    __shared__ float satt[256];
    __shared__ float sbias[32];
    __shared__ float colmax[16], colinv[16];
    __shared__ float spart[4 * 256];

    const int tid = threadIdx.x;
    const int n = blockIdx.x / S_;
    const int s = blockIdx.x % S_;

    for (int idx = tid; idx < IC_ * C_; idx += 256) {
        int i = idx >> 6, c = idx & 63;
        sWaT[c * 16 + i] = Wa[(s * IC_ + i) * C_ + c];
        sWbT[c * 16 + i] = Wb[(s * IC_ + i) * C_ + c];
    }
    if (tid < 16)      sbias[tid] = ba[s * 16 + tid];
    else if (tid < 32) sbias[tid] = bb[s * 16 + (tid - 16)];
    __syncthreads();

    const float* xn = x + (size_t)n * (C_ * T_ * V_);

    const int j0 = tid & 127;
    const int g = tid >> 7;
    const float* WT = g ? sWbT : sWaT;
    float* F = g ? sfb : sfa;
    unsigned long long bias2[8];
    #pragma unroll
    for (int q = 0; q < 8; q++)
        bias2[q] = pk2(sbias[g * 16 + 2 * q], sbias[g * 16 + 2 * q + 1]);

    const int kg = tid >> 6;
    const int v4 = (tid & 63) >> 2;
    const int wp = tid & 3;
    unsigned long long gacc[2];
    gacc[0] = 0ull; gacc[1] = 0ull;

    for (int t0 = 0; t0 < T_; t0 += 16) {
        for (int idx = tid; idx < 64 * 64; idx += 256) {
            int c = idx >> 6, q = idx & 63;
            reinterpret_cast<float4*>(sX + c * 256)[q] =
                reinterpret_cast<const float4*>(xn + (size_t)c * (T_ * V_) + t0 * V_)[q];
        }
        __syncthreads();

        {
            unsigned long long acc0[8], acc1[8];
            #pragma unroll
            for (int q = 0; q < 8; q++) { acc0[q] = bias2[q]; acc1[q] = bias2[q]; }
            #pragma unroll 4
            for (int c = 0; c < 64; c++) {
                float xv0 = sX[c * 256 + j0];
                float xv1 = sX[c * 256 + j0 + 128];
                unsigned long long x0 = pk2(xv0, xv0);
                unsigned long long x1 = pk2(xv1, xv1);
                const ulonglong2* w2 = reinterpret_cast<const ulonglong2*>(WT + c * 16);
                ulonglong2 p0 = w2[0];
                ulonglong2 p1 = w2[1];
                ffma2(acc0[0], x0, p0.x); ffma2(acc1[0], x1, p0.x);
                ffma2(acc0[1], x0, p0.y); ffma2(acc1[1], x1, p0.y);
                ffma2(acc0[2], x0, p1.x); ffma2(acc1[2], x1, p1.x);
                ffma2(acc0[3], x0, p1.y); ffma2(acc1[3], x1, p1.y);
                ulonglong2 p2 = w2[2];
                ulonglong2 p3 = w2[3];
                ffma2(acc0[4], x0, p2.x); ffma2(acc1[4], x1, p2.x);
                ffma2(acc0[5], x0, p2.y); ffma2(acc1[5], x1, p2.y);
                ffma2(acc0[6], x0, p3.x); ffma2(acc1[6], x1, p3.x);
                ffma2(acc0[7], x0, p3.y); ffma2(acc1[7], x1, p3.y);
            }
            #pragma unroll
            for (int q = 0; q < 8; q++) {
                float2 f0 = upk(acc0[q]);
                float2 f1 = upk(acc1[q]);
                F[(2 * q) * 256 + j0]           = f0.x;
                F[(2 * q + 1) * 256 + j0]       = f0.y;
                F[(2 * q) * 256 + j0 + 128]     = f1.x;
                F[(2 * q + 1) * 256 + j0 + 128] = f1.y;
            }
        }
        __syncthreads();

        {
            const float* pa = sfa + kg * 1024 + v4;
            const float* pb = sfb + kg * 1024 + wp * 4;
            #pragma unroll 8
            for (int u = 0; u < 64; u++) {
                float fav = pa[u * 16];
                unsigned long long fd = pk2(fav, fav);
                ulonglong2 fbp = *reinterpret_cast<const ulonglong2*>(pb + u * 16);
                ffma2(gacc[0], fd, fbp.x);
                ffma2(gacc[1], fd, fbp.y);
            }
        }
        __syncthreads();
    }

    {
        float2 g0 = upk(gacc[0]);
        float2 g1 = upk(gacc[1]);
        float* p = spart + kg * 256 + v4 * 16 + wp * 4;
        p[0] = g0.x; p[1] = g0.y; p[2] = g1.x; p[3] = g1.y;
    }
    __syncthreads();

    const int v = tid >> 4;
    const int w = tid & 15;
    float attacc = (spart[tid] + spart[256 + tid] + spart[512 + tid] +
                    spart[768 + tid]) * (1.0f / (float)(IC_ * T_));
    satt[tid] = attacc;
    __syncthreads();

    if (tid < 16) {
        float m = -1e30f;
        #pragma unroll
        for (int vv = 0; vv < 16; vv++) m = fmaxf(m, satt[vv * 16 + tid]);
        float ssum = 0.f;
        #pragma unroll
        for (int vv = 0; vv < 16; vv++) ssum += __expf(satt[vv * 16 + tid] - m);
        colmax[tid] = m;
        colinv[tid] = 1.0f / ssum;
    }
    __syncthreads();

    float r = __expf(attacc - colmax[w]) * colinv[w]
            + A_base[(s * 16 + v) * 16 + w] + PA[(s * 16 + v) * 16 + w];
    g_att[((n * 3 + s) * 16 + v) * 16 + w] = r;
}

// ---------------------------------------------------------------------------
// Kernel B: register-fused stage1 -> mma. Z never hits smem.
// warp wid owns t = t0+wid (rows wid*16..+15). Thread (lane) computes its
// exact A-fragment: rows (w, w+8), cols c ≡ kq (mod 4), via packed FFMA2.
// W staged per-s in u64 k-pair layout [kg=8][kq=4][66 u64] (conflict-free B).
// smem: sW 16896 @0 | att2 3072 @16896 | sX 32768 @20480 | sO 32768 @53248
// ---------------------------------------------------------------------------
__global__ __launch_bounds__(256, 2) void out_kernel(
    const float* __restrict__ x, const float* __restrict__ Wd,
    const float* __restrict__ bd, const float* __restrict__ gamma,
    const float* __restrict__ beta, float* __restrict__ out)
{
    extern __shared__ char smem[];
    unsigned long long* sW   = (unsigned long long*)(smem);          // [8][4][66]
    unsigned long long* sAtt2= (unsigned long long*)(smem + 16896);  // [3][16][8]
    float* sX = (float*)(smem + 20480);                              // [64][128]
    float* sO = (float*)(smem + 53248);                              // [64][128]

    __shared__ float sBN[3 * 64];

    const int tid  = threadIdx.x;
    const int wid  = tid >> 5;
    const int lane = tid & 31;
    const int n  = blockIdx.y;
    const int t0 = blockIdx.x * 8;

    const int kq   = lane & 3;
    const int wrow = lane >> 2;      // w = wrow, w+8 ; also m-row group
    const int ncol = lane >> 2;

    // W staging roles: thread owns o = tid&63, c-range 16*(tid>>6)..+15
    const int wo  = tid & 63;
    const int wkb = tid >> 6;
    const int wop = (wo & 7) * 8 + (wo >> 3);   // slot so ncol*8+nf <-> o=nf*8+ncol

    // ---- preamble
    for (int idx = tid; idx < 384; idx += 256) {
        int s = idx >> 7, rem = idx & 127;      // rem = v*8 + wp
        int v = rem >> 3, wp = rem & 7;
        const float* ap = g_att + n * 768 + s * 256 + v * 16 + wp;
        sAtt2[idx] = pk2(ap[0], ap[8]);
    }
    for (int idx = tid; idx < 64 * 32; idx += 256) {
        int c = idx >> 5, q = idx & 31;
        reinterpret_cast<float4*>(sX + c * 128)[q] =
            reinterpret_cast<const float4*>(x + (size_t)(n * 64 + c) * (T_ * V_) + t0 * V_)[q];
    }
    // W_0 -> sW
    {
        const float4* src = reinterpret_cast<const float4*>(Wd + (size_t)wo * 64 + wkb * 16);
        float4 wv[4];
        #pragma unroll
        for (int q = 0; q < 4; q++) wv[q] = src[q];
        const float* wf = (const float*)wv;     // c-offsets 0..15 from wkb*16
        #pragma unroll
        for (int kgl = 0; kgl < 2; kgl++) {     // kg = 2*wkb + kgl
            int kg = 2 * wkb + kgl;
            #pragma unroll
            for (int kql = 0; kql < 4; kql++) {
                uint32_t lo = f2tf32(wf[kgl * 8 + kql]);
                uint32_t hi = f2tf32(wf[kgl * 8 + kql + 4]);
                sW[(kg * 4 + kql) * 66 + wop] = ((unsigned long long)hi << 32) | lo;
            }
        }
    }
    if (tid < 64) {
        int o = tid;
        sBN[o]       = bd[o] + bd[64 + o] + bd[128 + o];
        sBN[64 + o]  = gamma[o] * rsqrtf(1.0f + 1e-5f);
        sBN[128 + o] = beta[o];
    }
    __syncthreads();

    float acc[8][4];
    #pragma unroll
    for (int nf = 0; nf < 8; nf++) {
        acc[nf][0] = 0.f; acc[nf][1] = 0.f; acc[nf][2] = 0.f; acc[nf][3] = 0.f;
    }

    const float* xrow_base = sX + wid * 16;   // + c*128

    #pragma unroll
    for (int s = 0; s < S_; s++) {
        // att2 regs: (att[v][w], att[v][w+8]) for this thread's w = wrow
        unsigned long long a2[16];
        #pragma unroll
        for (int v = 0; v < 16; v++)
            a2[v] = sAtt2[s * 128 + v * 8 + wrow];

        // ---- stage1 in registers: Zreg[p][j], c = 4j+kq, p: row w / w+8
        uint32_t Zr[2][16];
        #pragma unroll
        for (int j = 0; j < 16; j++) {
            const int c = 4 * j + kq;
            const float4* xp = reinterpret_cast<const float4*>(xrow_base + c * 128);
            float4 x0 = xp[0], x1 = xp[1], x2 = xp[2], x3 = xp[3];
            unsigned long long zacc = 0ull;
            ffma2(zacc, pk2(x0.x, x0.x), a2[0]);
            ffma2(zacc, pk2(x0.y, x0.y), a2[1]);
            ffma2(zacc, pk2(x0.z, x0.z), a2[2]);
            ffma2(zacc, pk2(x0.w, x0.w), a2[3]);
            ffma2(zacc, pk2(x1.x, x1.x), a2[4]);
            ffma2(zacc, pk2(x1.y, x1.y), a2[5]);
            ffma2(zacc, pk2(x1.z, x1.z), a2[6]);
            ffma2(zacc, pk2(x1.w, x1.w), a2[7]);
            ffma2(zacc, pk2(x2.x, x2.x), a2[8]);
            ffma2(zacc, pk2(x2.y, x2.y), a2[9]);
            ffma2(zacc, pk2(x2.z, x2.z), a2[10]);
            ffma2(zacc, pk2(x2.w, x2.w), a2[11]);
            ffma2(zacc, pk2(x3.x, x3.x), a2[12]);
            ffma2(zacc, pk2(x3.y, x3.y), a2[13]);
            ffma2(zacc, pk2(x3.z, x3.z), a2[14]);
            ffma2(zacc, pk2(x3.w, x3.w), a2[15]);
            float2 zf = upk(zacc);
            Zr[0][j] = f2tf32(zf.x);
            Zr[1][j] = f2tf32(zf.y);
        }

        // ---- prefetch W_{s+1} to regs (latency hidden behind stage2)
        float4 wv[4];
        if (s < 2) {
            const float4* src = reinterpret_cast<const float4*>(
                Wd + (size_t)(s + 1) * 4096 + (size_t)wo * 64 + wkb * 16);
            #pragma unroll
            for (int q = 0; q < 4; q++) wv[q] = src[q];
        }

        // ---- stage2: 8 k-steps, B via conflict-free LDS.128 of u64 pairs
        #pragma unroll
        for (int ks = 0; ks < 8; ks++) {
            const unsigned long long* brow = sW + (ks * 4 + kq) * 66 + ncol * 8;
            const uint32_t a0 = Zr[0][2 * ks];
            const uint32_t a1 = Zr[1][2 * ks];
            const uint32_t a2f = Zr[0][2 * ks + 1];
            const uint32_t a3 = Zr[1][2 * ks + 1];
            #pragma unroll
            for (int p = 0; p < 4; p++) {
                uint4 bb = *reinterpret_cast<const uint4*>(brow + 2 * p);
                // bb = {b0[nf=2p], b1[2p], b0[2p+1], b1[2p+1]}
                mma_tf32(acc[2 * p][0], acc[2 * p][1], acc[2 * p][2], acc[2 * p][3],
                         a0, a1, a2f, a3, bb.x, bb.y);
                mma_tf32(acc[2 * p + 1][0], acc[2 * p + 1][1], acc[2 * p + 1][2], acc[2 * p + 1][3],
                         a0, a1, a2f, a3, bb.z, bb.w);
            }
        }
        __syncthreads();   // all warps done reading sW (s)

        if (s < 2) {
            const float* wf = (const float*)wv;
            #pragma unroll
            for (int kgl = 0; kgl < 2; kgl++) {
                int kg = 2 * wkb + kgl;
                #pragma unroll
                for (int kql = 0; kql < 4; kql++) {
                    uint32_t lo = f2tf32(wf[kgl * 8 + kql]);
                    uint32_t hi = f2tf32(wf[kgl * 8 + kql + 4]);
                    sW[(kg * 4 + kql) * 66 + wop] = ((unsigned long long)hi << 32) | lo;
                }
            }
            __syncthreads();  // W_{s+1} published
        }
    }

    // ---- epilogue: BN+bias into sO[o][tw], then coalesced store + residual
    {
        const int r0 = wid * 16 + wrow;
        #pragma unroll
        for (int nf = 0; nf < 8; nf++) {
            int o0 = nf * 8 + 2 * (lane & 3);
            float s0 = sBN[64 + o0],     b0v = sBN[o0],     z0 = sBN[128 + o0];
            float s1 = sBN[64 + o0 + 1], b1v = sBN[o0 + 1], z1 = sBN[128 + o0 + 1];
            sO[o0 * 128 + r0]           = (acc[nf][0] + b0v) * s0 + z0;
            sO[(o0 + 1) * 128 + r0]     = (acc[nf][1] + b1v) * s1 + z1;
            sO[o0 * 128 + r0 + 8]       = (acc[nf][2] + b0v) * s0 + z0;
            sO[(o0 + 1) * 128 + r0 + 8] = (acc[nf][3] + b1v) * s1 + z1;
        }
    }
    __syncthreads();

    for (int idx = tid; idx < 64 * 32; idx += 256) {
        int c = idx >> 5, q = idx & 31;
        float4 yv = reinterpret_cast<const float4*>(sO + c * 128)[q];
        float4 xv = reinterpret_cast<const float4*>(sX + c * 128)[q];
        yv.x += xv.x; yv.y += xv.y; yv.z += xv.z; yv.w += xv.w;
        reinterpret_cast<float4*>(out + (size_t)(n * 64 + c) * (T_ * V_) + t0 * V_)[q] = yv;
    }
}

extern "C" void kernel_launch(void* const* d_in, const int* in_sizes, int n_in,
                              void* d_out, int out_size)
{
    const float* x      = (const float*)d_in[0];
    const float* A_base = (const float*)d_in[1];
    const float* PA     = (const float*)d_in[2];
    const float* Wa     = (const float*)d_in[3];
    const float* ba     = (const float*)d_in[4];
    const float* Wb     = (const float*)d_in[5];
    const float* bb     = (const float*)d_in[6];
    const float* Wd     = (const float*)d_in[7];
    const float* bd     = (const float*)d_in[8];
    const float* gamma  = (const float*)d_in[9];
    const float* beta   = (const float*)d_in[10];
    float* out = (float*)d_out;

    const int smemA = (1024 * 2 + 16384 + 4096 * 2) * sizeof(float);  // 106496 B
    const int smemB = 86016;                                          // bytes

    cudaFuncSetAttribute(attn_kernel, cudaFuncAttributeMaxDynamicSharedMemorySize, smemA);
    cudaFuncSetAttribute(out_kernel,  cudaFuncAttributeMaxDynamicSharedMemorySize, smemB);

    attn_kernel<<<N_ * S_, 256, smemA>>>(x, A_base, PA, Wa, ba, Wb, bb);
    out_kernel<<<dim3(T_ / 8, N_), 256, smemB>>>(x, Wd, bd, gamma, beta, out);
}

// round 8
// speedup vs baseline: 1.5240x; 1.5240x over previous
#include <cuda_runtime.h>
#include <cstdint>

#define N_  128
#define C_  64
#define T_  288
#define V_  16
#define S_  3
#define IC_ 16

// tiny scratch: attention matrices after softmax + A  [N, S, V, V]
__device__ float g_att[N_ * S_ * V_ * V_];

// ---- packed f32x2 helpers ------------------------------------------------
__device__ __forceinline__ unsigned long long pk2(float lo, float hi) {
    unsigned long long r;
    asm("mov.b64 %0, {%1, %2};" : "=l"(r) : "f"(lo), "f"(hi));
    return r;
}
__device__ __forceinline__ void ffma2(unsigned long long& acc,
                                      unsigned long long a,
                                      unsigned long long b) {
    asm("fma.rn.f32x2 %0, %1, %2, %0;" : "+l"(acc) : "l"(a), "l"(b));
}
__device__ __forceinline__ float2 upk(unsigned long long p) {
    float2 f;
    asm("mov.b64 {%0, %1}, %2;" : "=f"(f.x), "=f"(f.y) : "l"(p));
    return f;
}
__device__ __forceinline__ uint32_t f2tf32(float f) {
    uint32_t r;
    asm("cvt.rna.tf32.f32 %0, %1;" : "=r"(r) : "f"(f));
    return r;
}
__device__ __forceinline__ void mma_tf32(float& d0, float& d1, float& d2, float& d3,
                                         uint32_t a0, uint32_t a1, uint32_t a2, uint32_t a3,
                                         uint32_t b0, uint32_t b1) {
    asm volatile("mma.sync.aligned.m16n8k8.row.col.f32.tf32.tf32.f32 "
                 "{%0,%1,%2,%3}, {%4,%5,%6,%7}, {%8,%9}, {%0,%1,%2,%3};"
                 : "+f"(d0), "+f"(d1), "+f"(d2), "+f"(d3)
                 : "r"(a0), "r"(a1), "r"(a2), "r"(a3), "r"(b0), "r"(b1));
}

// ---------------------------------------------------------------------------
// Kernel A: unchanged from R6 (passing, ~309us)
// ---------------------------------------------------------------------------
__global__ __launch_bounds__(256, 2) void attn_kernel(
    const float* __restrict__ x, const float* __restrict__ A_base,
    const float* __restrict__ PA, const float* __restrict__ Wa,
    const float* __restrict__ ba, const float* __restrict__ Wb,
    const float* __restrict__ bb)
{
    extern __shared__ float smemf[];
    float* sWaT = smemf;               // [64][16]
    float* sWbT = sWaT + 1024;         // [64][16]
    float* sX   = sWbT + 1024;         // [64][256]
    float* sfa  = sX + 16384;          // [16][256]
    float* sfb  = sfa + 4096;          // [16][256]

    __shared__ float satt[256];
    __shared__ float sbias[32];
    __shared__ float colmax[16], colinv[16];
    __shared__ float spart[4 * 256];

    const int tid = threadIdx.x;
    const int n = blockIdx.x / S_;
    const int s = blockIdx.x % S_;

    for (int idx = tid; idx < IC_ * C_; idx += 256) {
        int i = idx >> 6, c = idx & 63;
        sWaT[c * 16 + i] = Wa[(s * IC_ + i) * C_ + c];
        sWbT[c * 16 + i] = Wb[(s * IC_ + i) * C_ + c];
    }
    if (tid < 16)      sbias[tid] = ba[s * 16 + tid];
    else if (tid < 32) sbias[tid] = bb[s * 16 + (tid - 16)];
    __syncthreads();

    const float* xn = x + (size_t)n * (C_ * T_ * V_);

    const int j0 = tid & 127;
    const int g = tid >> 7;
    const float* WT = g ? sWbT : sWaT;
    float* F = g ? sfb : sfa;
    unsigned long long bias2[8];
    #pragma unroll
    for (int q = 0; q < 8; q++)
        bias2[q] = pk2(sbias[g * 16 + 2 * q], sbias[g * 16 + 2 * q + 1]);

    const int kg = tid >> 6;
    const int v4 = (tid & 63) >> 2;
    const int wp = tid & 3;
    unsigned long long gacc[2];
    gacc[0] = 0ull; gacc[1] = 0ull;

    for (int t0 = 0; t0 < T_; t0 += 16) {
        for (int idx = tid; idx < 64 * 64; idx += 256) {
            int c = idx >> 6, q = idx & 63;
            reinterpret_cast<float4*>(sX + c * 256)[q] =
                reinterpret_cast<const float4*>(xn + (size_t)c * (T_ * V_) + t0 * V_)[q];
        }
        __syncthreads();

        {
            unsigned long long acc0[8], acc1[8];
            #pragma unroll
            for (int q = 0; q < 8; q++) { acc0[q] = bias2[q]; acc1[q] = bias2[q]; }
            #pragma unroll 4
            for (int c = 0; c < 64; c++) {
                float xv0 = sX[c * 256 + j0];
                float xv1 = sX[c * 256 + j0 + 128];
                unsigned long long x0 = pk2(xv0, xv0);
                unsigned long long x1 = pk2(xv1, xv1);
                const ulonglong2* w2 = reinterpret_cast<const ulonglong2*>(WT + c * 16);
                ulonglong2 p0 = w2[0];
                ulonglong2 p1 = w2[1];
                ffma2(acc0[0], x0, p0.x); ffma2(acc1[0], x1, p0.x);
                ffma2(acc0[1], x0, p0.y); ffma2(acc1[1], x1, p0.y);
                ffma2(acc0[2], x0, p1.x); ffma2(acc1[2], x1, p1.x);
                ffma2(acc0[3], x0, p1.y); ffma2(acc1[3], x1, p1.y);
                ulonglong2 p2 = w2[2];
                ulonglong2 p3 = w2[3];
                ffma2(acc0[4], x0, p2.x); ffma2(acc1[4], x1, p2.x);
                ffma2(acc0[5], x0, p2.y); ffma2(acc1[5], x1, p2.y);
                ffma2(acc0[6], x0, p3.x); ffma2(acc1[6], x1, p3.x);
                ffma2(acc0[7], x0, p3.y); ffma2(acc1[7], x1, p3.y);
            }
            #pragma unroll
            for (int q = 0; q < 8; q++) {
                float2 f0 = upk(acc0[q]);
                float2 f1 = upk(acc1[q]);
                F[(2 * q) * 256 + j0]           = f0.x;
                F[(2 * q + 1) * 256 + j0]       = f0.y;
                F[(2 * q) * 256 + j0 + 128]     = f1.x;
                F[(2 * q + 1) * 256 + j0 + 128] = f1.y;
            }
        }
        __syncthreads();

        {
            const float* pa = sfa + kg * 1024 + v4;
            const float* pb = sfb + kg * 1024 + wp * 4;
            #pragma unroll 8
            for (int u = 0; u < 64; u++) {
                float fav = pa[u * 16];
                unsigned long long fd = pk2(fav, fav);
                ulonglong2 fbp = *reinterpret_cast<const ulonglong2*>(pb + u * 16);
                ffma2(gacc[0], fd, fbp.x);
                ffma2(gacc[1], fd, fbp.y);
            }
        }
        __syncthreads();
    }

    {
        float2 g0 = upk(gacc[0]);
        float2 g1 = upk(gacc[1]);
        float* p = spart + kg * 256 + v4 * 16 + wp * 4;
        p[0] = g0.x; p[1] = g0.y; p[2] = g1.x; p[3] = g1.y;
    }
    __syncthreads();

    const int v = tid >> 4;
    const int w = tid & 15;
    float attacc = (spart[tid] + spart[256 + tid] + spart[512 + tid] +
                    spart[768 + tid]) * (1.0f / (float)(IC_ * T_));
    satt[tid] = attacc;
    __syncthreads();

    if (tid < 16) {
        float m = -1e30f;
        #pragma unroll
        for (int vv = 0; vv < 16; vv++) m = fmaxf(m, satt[vv * 16 + tid]);
        float ssum = 0.f;
        #pragma unroll
        for (int vv = 0; vv < 16; vv++) ssum += __expf(satt[vv * 16 + tid] - m);
        colmax[tid] = m;
        colinv[tid] = 1.0f / ssum;
    }
    __syncthreads();

    float r = __expf(attacc - colmax[w]) * colinv[w]
            + A_base[(s * 16 + v) * 16 + w] + PA[(s * 16 + v) * 16 + w];
    g_att[((n * 3 + s) * 16 + v) * 16 + w] = r;
}

// ---------------------------------------------------------------------------
// Kernel B (R5 structure, bank-conflict-fixed):
//   stage1 (FFMA2): Z_s[tw=128][c=64] tf32, pitch 74 (conflict-free STS+LDS)
//   stage2 (mma.sync m16n8k8): D[128tw,64o] += Z_s @ W_s[c][o] (pitch 72)
//   sX / sO pitch 132 (conflict-free x reads + epilogue stores)
// smem: sZ 37888 @0 (sO reuses) | sW0 @37888 | sW1 @56320 | sX @74752 | att @108544
// ---------------------------------------------------------------------------
#define ZP 74
#define WP 72
#define XP 132
__global__ __launch_bounds__(256, 2) void out_kernel(
    const float* __restrict__ x, const float* __restrict__ Wd,
    const float* __restrict__ bd, const float* __restrict__ gamma,
    const float* __restrict__ beta, float* __restrict__ out)
{
    extern __shared__ char smem[];
    uint32_t* sZ  = (uint32_t*)(smem);                 // [128][ZP] tf32
    float*    sO  = (float*)(smem);                    // epilogue reuse [64][XP]
    uint32_t* sW0 = (uint32_t*)(smem + 37888);         // [64][WP] tf32
    uint32_t* sW1 = (uint32_t*)(smem + 56320);
    float*    sX  = (float*)(smem + 74752);            // [64][XP]
    float*    sAtt= (float*)(smem + 108544);           // [3][16][16]

    __shared__ float sBN[3 * 64];

    const int tid  = threadIdx.x;
    const int wid  = tid >> 5;
    const int lane = tid & 31;
    const int n  = blockIdx.y;
    const int t0 = blockIdx.x * 8;

    // preamble: att, x tile, W_0, BN constants
    for (int idx = tid; idx < 768; idx += 256)
        sAtt[idx] = g_att[n * 768 + idx];
    for (int idx = tid; idx < 64 * 32; idx += 256) {
        int c = idx >> 5, q = idx & 31;
        reinterpret_cast<float4*>(sX + c * XP)[q] =
            reinterpret_cast<const float4*>(x + (size_t)(n * 64 + c) * (T_ * V_) + t0 * V_)[q];
    }
    #pragma unroll
    for (int q = 0; q < 4; q++) {
        int i4 = tid * 4 + q;              // o = i4>>4, c-quad = i4&15
        int o = i4 >> 4, c4 = i4 & 15;
        float4 wv = reinterpret_cast<const float4*>(Wd)[i4];
        sW0[(c4 * 4 + 0) * WP + o] = f2tf32(wv.x);
        sW0[(c4 * 4 + 1) * WP + o] = f2tf32(wv.y);
        sW0[(c4 * 4 + 2) * WP + o] = f2tf32(wv.z);
        sW0[(c4 * 4 + 3) * WP + o] = f2tf32(wv.w);
    }
    if (tid < 64) {
        int o = tid;
        sBN[o]       = bd[o] + bd[64 + o] + bd[128 + o];
        sBN[64 + o]  = gamma[o] * rsqrtf(1.0f + 1e-5f);
        sBN[128 + o] = beta[o];
    }
    __syncthreads();

    // stage1 roles
    const int c1 = tid >> 2;
    const int wg = tid & 3;

    // mma roles
    const int m0   = wid * 16;
    const int rA0  = m0 + (lane >> 2);
    const int kq   = lane & 3;
    const int ncol = lane >> 2;

    float acc[8][4];
    #pragma unroll
    for (int nf = 0; nf < 8; nf++) {
        acc[nf][0] = 0.f; acc[nf][1] = 0.f; acc[nf][2] = 0.f; acc[nf][3] = 0.f;
    }

    #pragma unroll
    for (int s = 0; s < S_; s++) {
        uint32_t* sWcur = (s & 1) ? sW1 : sW0;

        // ---- stage1: Z_s[tw][c1] tf32 (conflict-free stores with ZP=74)
        ulonglong2 ar[16];
        #pragma unroll
        for (int v = 0; v < 16; v++)
            ar[v] = *reinterpret_cast<const ulonglong2*>(sAtt + s * 256 + v * 16 + wg * 4);

        #pragma unroll
        for (int tt = 0; tt < 8; tt++) {
            const float4* xp = reinterpret_cast<const float4*>(sX + c1 * XP + tt * 16);
            float xr[16];
            #pragma unroll
            for (int q = 0; q < 4; q++) {
                float4 xx = xp[q];
                xr[q * 4 + 0] = xx.x; xr[q * 4 + 1] = xx.y;
                xr[q * 4 + 2] = xx.z; xr[q * 4 + 3] = xx.w;
            }
            unsigned long long a0 = 0ull, a1 = 0ull;
            #pragma unroll
            for (int v = 0; v < 16; v++) {
                unsigned long long xd = pk2(xr[v], xr[v]);
                ffma2(a0, xd, ar[v].x);
                ffma2(a1, xd, ar[v].y);
            }
            float2 f0 = upk(a0), f1 = upk(a1);
            const int twb = tt * 16 + wg * 4;
            sZ[(twb + 0) * ZP + c1] = f2tf32(f0.x);
            sZ[(twb + 1) * ZP + c1] = f2tf32(f0.y);
            sZ[(twb + 2) * ZP + c1] = f2tf32(f1.x);
            sZ[(twb + 3) * ZP + c1] = f2tf32(f1.y);
        }

        // prefetch W_{s+1} into other buffer
        if (s < 2) {
            uint32_t* sWn = ((s + 1) & 1) ? sW1 : sW0;
            const float4* src = reinterpret_cast<const float4*>(Wd + (size_t)(s + 1) * 4096);
            #pragma unroll
            for (int q = 0; q < 4; q++) {
                int i4 = tid * 4 + q;
                int o = i4 >> 4, c4 = i4 & 15;
                float4 wv = src[i4];
                sWn[(c4 * 4 + 0) * WP + o] = f2tf32(wv.x);
                sWn[(c4 * 4 + 1) * WP + o] = f2tf32(wv.y);
                sWn[(c4 * 4 + 2) * WP + o] = f2tf32(wv.z);
                sWn[(c4 * 4 + 3) * WP + o] = f2tf32(wv.w);
            }
        }
        __syncthreads();   // Z_s + W visible

        // ---- stage2: 8 k-steps of m16n8k8 over c
        #pragma unroll
        for (int ks = 0; ks < 8; ks++) {
            const int k0 = ks * 8;
            uint32_t a0 = sZ[rA0 * ZP + k0 + kq];
            uint32_t a1 = sZ[(rA0 + 8) * ZP + k0 + kq];
            uint32_t a2 = sZ[rA0 * ZP + k0 + 4 + kq];
            uint32_t a3 = sZ[(rA0 + 8) * ZP + k0 + 4 + kq];
            const uint32_t* bp0 = sWcur + (k0 + kq) * WP + ncol;
            const uint32_t* bp1 = sWcur + (k0 + 4 + kq) * WP + ncol;
            #pragma unroll
            for (int nf = 0; nf < 8; nf++) {
                uint32_t b0 = bp0[nf * 8];
                uint32_t b1 = bp1[nf * 8];
                mma_tf32(acc[nf][0], acc[nf][1], acc[nf][2], acc[nf][3],
                         a0, a1, a2, a3, b0, b1);
            }
        }
        __syncthreads();   // done reading Z_s before next stage1 overwrites
    }

    // ---- epilogue: BN+bias into sO[o][tw] (pitch 132, conflict-free)
    {
        const int r0 = m0 + (lane >> 2);
        #pragma unroll
        for (int nf = 0; nf < 8; nf++) {
            int o0 = nf * 8 + 2 * (lane & 3);
            float s0 = sBN[64 + o0],     b0v = sBN[o0],     z0 = sBN[128 + o0];
            float s1 = sBN[64 + o0 + 1], b1v = sBN[o0 + 1], z1 = sBN[128 + o0 + 1];
            sO[o0 * XP + r0]           = (acc[nf][0] + b0v) * s0 + z0;
            sO[(o0 + 1) * XP + r0]     = (acc[nf][1] + b1v) * s1 + z1;
            sO[o0 * XP + r0 + 8]       = (acc[nf][2] + b0v) * s0 + z0;
            sO[(o0 + 1) * XP + r0 + 8] = (acc[nf][3] + b1v) * s1 + z1;
        }
    }
    __syncthreads();

    for (int idx = tid; idx < 64 * 32; idx += 256) {
        int c = idx >> 5, q = idx & 31;
        float4 yv = reinterpret_cast<const float4*>(sO + c * XP)[q];
        float4 xv = reinterpret_cast<const float4*>(sX + c * XP)[q];
        yv.x += xv.x; yv.y += xv.y; yv.z += xv.z; yv.w += xv.w;
        reinterpret_cast<float4*>(out + (size_t)(n * 64 + c) * (T_ * V_) + t0 * V_)[q] = yv;
    }
}

extern "C" void kernel_launch(void* const* d_in, const int* in_sizes, int n_in,
                              void* d_out, int out_size)
{
    const float* x      = (const float*)d_in[0];
    const float* A_base = (const float*)d_in[1];
    const float* PA     = (const float*)d_in[2];
    const float* Wa     = (const float*)d_in[3];
    const float* ba     = (const float*)d_in[4];
    const float* Wb     = (const float*)d_in[5];
    const float* bb     = (const float*)d_in[6];
    const float* Wd     = (const float*)d_in[7];
    const float* bd     = (const float*)d_in[8];
    const float* gamma  = (const float*)d_in[9];
    const float* beta   = (const float*)d_in[10];
    float* out = (float*)d_out;

    const int smemA = (1024 * 2 + 16384 + 4096 * 2) * sizeof(float);  // 106496 B
    const int smemB = 111616;                                         // bytes

    cudaFuncSetAttribute(attn_kernel, cudaFuncAttributeMaxDynamicSharedMemorySize, smemA);
    cudaFuncSetAttribute(out_kernel,  cudaFuncAttributeMaxDynamicSharedMemorySize, smemB);

    attn_kernel<<<N_ * S_, 256, smemA>>>(x, A_base, PA, Wa, ba, Wb, bb);
    out_kernel<<<dim3(T_ / 8, N_), 256, smemB>>>(x, Wd, bd, gamma, beta, out);
}

// round 9
// speedup vs baseline: 1.7309x; 1.1357x over previous
#include <cuda_runtime.h>
#include <cstdint>

#define N_  128
#define C_  64
#define T_  288
#define V_  16
#define S_  3
#define IC_ 16

// tiny scratch: attention matrices after softmax + A  [N, S, V, V]
__device__ float g_att[N_ * S_ * V_ * V_];

// ---- packed f32x2 helpers ------------------------------------------------
__device__ __forceinline__ unsigned long long pk2(float lo, float hi) {
    unsigned long long r;
    asm("mov.b64 %0, {%1, %2};" : "=l"(r) : "f"(lo), "f"(hi));
    return r;
}
__device__ __forceinline__ void ffma2(unsigned long long& acc,
                                      unsigned long long a,
                                      unsigned long long b) {
    asm("fma.rn.f32x2 %0, %1, %2, %0;" : "+l"(acc) : "l"(a), "l"(b));
}
__device__ __forceinline__ float2 upk(unsigned long long p) {
    float2 f;
    asm("mov.b64 {%0, %1}, %2;" : "=f"(f.x), "=f"(f.y) : "l"(p));
    return f;
}
__device__ __forceinline__ uint32_t f2tf32(float f) {
    uint32_t r;
    asm("cvt.rna.tf32.f32 %0, %1;" : "=r"(r) : "f"(f));
    return r;
}
__device__ __forceinline__ void mma_tf32(float& d0, float& d1, float& d2, float& d3,
                                         uint32_t a0, uint32_t a1, uint32_t a2, uint32_t a3,
                                         uint32_t b0, uint32_t b1) {
    asm volatile("mma.sync.aligned.m16n8k8.row.col.f32.tf32.tf32.f32 "
                 "{%0,%1,%2,%3}, {%4,%5,%6,%7}, {%8,%9}, {%0,%1,%2,%3};"
                 : "+f"(d0), "+f"(d1), "+f"(d2), "+f"(d3)
                 : "r"(a0), "r"(a1), "r"(a2), "r"(a3), "r"(b0), "r"(b1));
}

// ---------------------------------------------------------------------------
// Kernel A (tensor): per (n,s), per 16-t chunk:
//   phase1: F[32][256] = Wab[32][64] @ xchunk[64][256]  (fa rows 0-15 + bias,
//           fb rows 16-31 + bias), m16n8k8 tf32, operands = raw fp32 bits
//   phase2: gram[16v][16w] += F[0:16]^T-slices @ F[16:32] over k=(i,t)
//           (each warp owns 32 k; fragments accumulate across all 18 chunks)
//   tail: cross-warp reduce, /(IC*T), softmax over v, +A_base+PA -> g_att
// dyn smem: sXc [64][264] | sF [32][264] | sWab [32][72] | spart [8][256]
// ---------------------------------------------------------------------------
#define XCP 264
#define WABP 72
__global__ __launch_bounds__(256) void attn_kernel(
    const float* __restrict__ x, const float* __restrict__ A_base,
    const float* __restrict__ PA, const float* __restrict__ Wa,
    const float* __restrict__ ba, const float* __restrict__ Wb,
    const float* __restrict__ bb)
{
    extern __shared__ float sm[];
    float* sXc   = sm;                          // [64][264]
    float* sF    = sm + 64 * XCP;               // [32][264]
    float* sWab  = sm + 64 * XCP + 32 * XCP;    // [32][72]
    float* spart = sWab + 32 * WABP;            // [8][256]

    __shared__ float sbias[32];
    __shared__ float satt[256];
    __shared__ float colmax[16], colinv[16];

    const int tid  = threadIdx.x;
    const int wid  = tid >> 5;
    const int lane = tid & 31;
    const int n = blockIdx.x / S_;
    const int s = blockIdx.x % S_;

    const int r    = lane >> 2;
    const int kq   = lane & 3;
    const int ncol = lane >> 2;

    // ---- Wab -> smem (fa rows 0-15, fb rows 16-31), raw fp32 bits
    {
        int i = tid >> 3, c8 = (tid & 7) * 8;
        const float* src = (i < 16)
            ? (Wa + (size_t)(s * 16 + i) * 64 + c8)
            : (Wb + (size_t)(s * 16 + (i - 16)) * 64 + c8);
        *reinterpret_cast<float4*>(sWab + i * WABP + c8)     = *reinterpret_cast<const float4*>(src);
        *reinterpret_cast<float4*>(sWab + i * WABP + c8 + 4) = *reinterpret_cast<const float4*>(src + 4);
    }
    if (tid < 16)      sbias[tid] = ba[s * 16 + tid];
    else if (tid < 32) sbias[tid] = bb[s * 16 + (tid - 16)];

    const float* xn = x + (size_t)n * (C_ * T_ * V_);

    // ---- chunk 0 x load
    for (int idx = tid; idx < 4096; idx += 256) {
        int c = idx >> 6, q = idx & 63;
        *reinterpret_cast<float4*>(sXc + c * XCP + q * 4) =
            *reinterpret_cast<const float4*>(xn + (size_t)c * (T_ * V_) + q * 4);
    }
    __syncthreads();

    // phase1 roles: m-tile (fa/fb) and 64-col slab
    const int mt = wid & 1;
    const int n0 = (wid >> 1) * 64;
    const float b_r  = sbias[mt * 16 + r];
    const float b_r8 = sbias[mt * 16 + r + 8];
    const int row0 = mt * 16 + r;

    float gacc[2][4];
    gacc[0][0] = 0.f; gacc[0][1] = 0.f; gacc[0][2] = 0.f; gacc[0][3] = 0.f;
    gacc[1][0] = 0.f; gacc[1][1] = 0.f; gacc[1][2] = 0.f; gacc[1][3] = 0.f;

    const uint32_t* uWab = reinterpret_cast<const uint32_t*>(sWab);
    const uint32_t* uXc  = reinterpret_cast<const uint32_t*>(sXc);
    const uint32_t* uF   = reinterpret_cast<const uint32_t*>(sF);

    for (int ch = 0; ch < 18; ch++) {
        // ---- phase1: F = Wab @ xchunk  (+bias)
        float acc[8][4];
        #pragma unroll
        for (int nt = 0; nt < 8; nt++) {
            acc[nt][0] = b_r; acc[nt][1] = b_r;
            acc[nt][2] = b_r8; acc[nt][3] = b_r8;
        }
        #pragma unroll
        for (int ks = 0; ks < 8; ks++) {
            const int k0 = ks * 8;
            uint32_t a0 = uWab[row0 * WABP + k0 + kq];
            uint32_t a1 = uWab[(row0 + 8) * WABP + k0 + kq];
            uint32_t a2 = uWab[row0 * WABP + k0 + 4 + kq];
            uint32_t a3 = uWab[(row0 + 8) * WABP + k0 + 4 + kq];
            const uint32_t* bp0 = uXc + (k0 + kq) * XCP + n0 + ncol;
            const uint32_t* bp1 = uXc + (k0 + 4 + kq) * XCP + n0 + ncol;
            #pragma unroll
            for (int nt = 0; nt < 8; nt++) {
                mma_tf32(acc[nt][0], acc[nt][1], acc[nt][2], acc[nt][3],
                         a0, a1, a2, a3, bp0[nt * 8], bp1[nt * 8]);
            }
        }
        #pragma unroll
        for (int nt = 0; nt < 8; nt++) {
            const int col = n0 + nt * 8 + 2 * kq;
            *reinterpret_cast<float2*>(sF + row0 * XCP + col) =
                make_float2(acc[nt][0], acc[nt][1]);
            *reinterpret_cast<float2*>(sF + (row0 + 8) * XCP + col) =
                make_float2(acc[nt][2], acc[nt][3]);
        }
        __syncthreads();   // F ready; sXc fully consumed

        // ---- x load for next chunk (overlaps phase2)
        if (ch < 17) {
            const float* src = xn + (ch + 1) * 256;
            for (int idx = tid; idx < 4096; idx += 256) {
                int c = idx >> 6, q = idx & 63;
                *reinterpret_cast<float4*>(sXc + c * XCP + q * 4) =
                    *reinterpret_cast<const float4*>(src + (size_t)c * (T_ * V_) + q * 4);
            }
        }

        // ---- phase2: gram += fa^T @ fb over this chunk's 256 k (warp owns 32)
        {
            const int kb = wid * 32;
            #pragma unroll
            for (int ks = 0; ks < 4; ks++) {
                const int k0 = kb + ks * 8;
                const int i  = k0 >> 4;
                const int tb = k0 & 8;
                uint32_t a0 = uF[i * XCP + (tb + kq) * 16 + r];
                uint32_t a1 = uF[i * XCP + (tb + kq) * 16 + r + 8];
                uint32_t a2 = uF[i * XCP + (tb + kq + 4) * 16 + r];
                uint32_t a3 = uF[i * XCP + (tb + kq + 4) * 16 + r + 8];
                #pragma unroll
                for (int nt = 0; nt < 2; nt++) {
                    uint32_t b0 = uF[(16 + i) * XCP + (tb + kq) * 16 + nt * 8 + ncol];
                    uint32_t b1 = uF[(16 + i) * XCP + (tb + kq + 4) * 16 + nt * 8 + ncol];
                    mma_tf32(gacc[nt][0], gacc[nt][1], gacc[nt][2], gacc[nt][3],
                             a0, a1, a2, a3, b0, b1);
                }
            }
        }
        __syncthreads();   // phase2 done reading sF; sXc(ch+1) ready
    }

    // ---- cross-warp reduce of gram partials
    #pragma unroll
    for (int nt = 0; nt < 2; nt++) {
        float* p = spart + wid * 256 + nt * 8 + 2 * kq;
        p[r * 16]           = gacc[nt][0];
        p[r * 16 + 1]       = gacc[nt][1];
        p[(r + 8) * 16]     = gacc[nt][2];
        p[(r + 8) * 16 + 1] = gacc[nt][3];
    }
    __syncthreads();

    float attacc = 0.f;
    #pragma unroll
    for (int w8 = 0; w8 < 8; w8++) attacc += spart[w8 * 256 + tid];
    attacc *= (1.0f / (float)(IC_ * T_));
    satt[tid] = attacc;
    __syncthreads();

    const int v = tid >> 4;
    const int w = tid & 15;
    if (tid < 16) {
        float m = -1e30f;
        #pragma unroll
        for (int vv = 0; vv < 16; vv++) m = fmaxf(m, satt[vv * 16 + tid]);
        float ssum = 0.f;
        #pragma unroll
        for (int vv = 0; vv < 16; vv++) ssum += __expf(satt[vv * 16 + tid] - m);
        colmax[tid] = m;
        colinv[tid] = 1.0f / ssum;
    }
    __syncthreads();

    float rr = __expf(attacc - colmax[w]) * colinv[w]
             + A_base[(s * 16 + v) * 16 + w] + PA[(s * 16 + v) * 16 + w];
    g_att[((n * 3 + s) * 16 + v) * 16 + w] = rr;
}

// ---------------------------------------------------------------------------
// Kernel B: unchanged from R8 (passing, 276us)
// ---------------------------------------------------------------------------
#define ZP 74
#define WP 72
#define XP 132
__global__ __launch_bounds__(256, 2) void out_kernel(
    const float* __restrict__ x, const float* __restrict__ Wd,
    const float* __restrict__ bd, const float* __restrict__ gamma,
    const float* __restrict__ beta, float* __restrict__ out)
{
    extern __shared__ char smem[];
    uint32_t* sZ  = (uint32_t*)(smem);                 // [128][ZP] tf32
    float*    sO  = (float*)(smem);                    // epilogue reuse [64][XP]
    uint32_t* sW0 = (uint32_t*)(smem + 37888);         // [64][WP] tf32
    uint32_t* sW1 = (uint32_t*)(smem + 56320);
    float*    sX  = (float*)(smem + 74752);            // [64][XP]
    float*    sAtt= (float*)(smem + 108544);           // [3][16][16]

    __shared__ float sBN[3 * 64];

    const int tid  = threadIdx.x;
    const int wid  = tid >> 5;
    const int lane = tid & 31;
    const int n  = blockIdx.y;
    const int t0 = blockIdx.x * 8;

    for (int idx = tid; idx < 768; idx += 256)
        sAtt[idx] = g_att[n * 768 + idx];
    for (int idx = tid; idx < 64 * 32; idx += 256) {
        int c = idx >> 5, q = idx & 31;
        reinterpret_cast<float4*>(sX + c * XP)[q] =
            reinterpret_cast<const float4*>(x + (size_t)(n * 64 + c) * (T_ * V_) + t0 * V_)[q];
    }
    #pragma unroll
    for (int q = 0; q < 4; q++) {
        int i4 = tid * 4 + q;
        int o = i4 >> 4, c4 = i4 & 15;
        float4 wv = reinterpret_cast<const float4*>(Wd)[i4];
        sW0[(c4 * 4 + 0) * WP + o] = f2tf32(wv.x);
        sW0[(c4 * 4 + 1) * WP + o] = f2tf32(wv.y);
        sW0[(c4 * 4 + 2) * WP + o] = f2tf32(wv.z);
        sW0[(c4 * 4 + 3) * WP + o] = f2tf32(wv.w);
    }
    if (tid < 64) {
        int o = tid;
        sBN[o]       = bd[o] + bd[64 + o] + bd[128 + o];
        sBN[64 + o]  = gamma[o] * rsqrtf(1.0f + 1e-5f);
        sBN[128 + o] = beta[o];
    }
    __syncthreads();

    const int c1 = tid >> 2;
    const int wg = tid & 3;

    const int m0   = wid * 16;
    const int rA0  = m0 + (lane >> 2);
    const int kq   = lane & 3;
    const int ncol = lane >> 2;

    float acc[8][4];
    #pragma unroll
    for (int nf = 0; nf < 8; nf++) {
        acc[nf][0] = 0.f; acc[nf][1] = 0.f; acc[nf][2] = 0.f; acc[nf][3] = 0.f;
    }

    #pragma unroll
    for (int s = 0; s < S_; s++) {
        uint32_t* sWcur = (s & 1) ? sW1 : sW0;

        ulonglong2 ar[16];
        #pragma unroll
        for (int v = 0; v < 16; v++)
            ar[v] = *reinterpret_cast<const ulonglong2*>(sAtt + s * 256 + v * 16 + wg * 4);

        #pragma unroll
        for (int tt = 0; tt < 8; tt++) {
            const float4* xp = reinterpret_cast<const float4*>(sX + c1 * XP + tt * 16);
            float xr[16];
            #pragma unroll
            for (int q = 0; q < 4; q++) {
                float4 xx = xp[q];
                xr[q * 4 + 0] = xx.x; xr[q * 4 + 1] = xx.y;
                xr[q * 4 + 2] = xx.z; xr[q * 4 + 3] = xx.w;
            }
            unsigned long long a0 = 0ull, a1 = 0ull;
            #pragma unroll
            for (int v = 0; v < 16; v++) {
                unsigned long long xd = pk2(xr[v], xr[v]);
                ffma2(a0, xd, ar[v].x);
                ffma2(a1, xd, ar[v].y);
            }
            float2 f0 = upk(a0), f1 = upk(a1);
            const int twb = tt * 16 + wg * 4;
            sZ[(twb + 0) * ZP + c1] = f2tf32(f0.x);
            sZ[(twb + 1) * ZP + c1] = f2tf32(f0.y);
            sZ[(twb + 2) * ZP + c1] = f2tf32(f1.x);
            sZ[(twb + 3) * ZP + c1] = f2tf32(f1.y);
        }

        if (s < 2) {
            uint32_t* sWn = ((s + 1) & 1) ? sW1 : sW0;
            const float4* src = reinterpret_cast<const float4*>(Wd + (size_t)(s + 1) * 4096);
            #pragma unroll
            for (int q = 0; q < 4; q++) {
                int i4 = tid * 4 + q;
                int o = i4 >> 4, c4 = i4 & 15;
                float4 wv = src[i4];
                sWn[(c4 * 4 + 0) * WP + o] = f2tf32(wv.x);
                sWn[(c4 * 4 + 1) * WP + o] = f2tf32(wv.y);
                sWn[(c4 * 4 + 2) * WP + o] = f2tf32(wv.z);
                sWn[(c4 * 4 + 3) * WP + o] = f2tf32(wv.w);
            }
        }
        __syncthreads();

        #pragma unroll
        for (int ks = 0; ks < 8; ks++) {
            const int k0 = ks * 8;
            uint32_t a0 = sZ[rA0 * ZP + k0 + kq];
            uint32_t a1 = sZ[(rA0 + 8) * ZP + k0 + kq];
            uint32_t a2 = sZ[rA0 * ZP + k0 + 4 + kq];
            uint32_t a3 = sZ[(rA0 + 8) * ZP + k0 + 4 + kq];
            const uint32_t* bp0 = sWcur + (k0 + kq) * WP + ncol;
            const uint32_t* bp1 = sWcur + (k0 + 4 + kq) * WP + ncol;
            #pragma unroll
            for (int nf = 0; nf < 8; nf++) {
                uint32_t b0 = bp0[nf * 8];
                uint32_t b1 = bp1[nf * 8];
                mma_tf32(acc[nf][0], acc[nf][1], acc[nf][2], acc[nf][3],
                         a0, a1, a2, a3, b0, b1);
            }
        }
        __syncthreads();
    }

    {
        const int r0 = m0 + (lane >> 2);
        #pragma unroll
        for (int nf = 0; nf < 8; nf++) {
            int o0 = nf * 8 + 2 * (lane & 3);
            float s0 = sBN[64 + o0],     b0v = sBN[o0],     z0 = sBN[128 + o0];
            float s1 = sBN[64 + o0 + 1], b1v = sBN[o0 + 1], z1 = sBN[128 + o0 + 1];
            sO[o0 * XP + r0]           = (acc[nf][0] + b0v) * s0 + z0;
            sO[(o0 + 1) * XP + r0]     = (acc[nf][1] + b1v) * s1 + z1;
            sO[o0 * XP + r0 + 8]       = (acc[nf][2] + b0v) * s0 + z0;
            sO[(o0 + 1) * XP + r0 + 8] = (acc[nf][3] + b1v) * s1 + z1;
        }
    }
    __syncthreads();

    for (int idx = tid; idx < 64 * 32; idx += 256) {
        int c = idx >> 5, q = idx & 31;
        float4 yv = reinterpret_cast<const float4*>(sO + c * XP)[q];
        float4 xv = reinterpret_cast<const float4*>(sX + c * XP)[q];
        yv.x += xv.x; yv.y += xv.y; yv.z += xv.z; yv.w += xv.w;
        reinterpret_cast<float4*>(out + (size_t)(n * 64 + c) * (T_ * V_) + t0 * V_)[q] = yv;
    }
}

extern "C" void kernel_launch(void* const* d_in, const int* in_sizes, int n_in,
                              void* d_out, int out_size)
{
    const float* x      = (const float*)d_in[0];
    const float* A_base = (const float*)d_in[1];
    const float* PA     = (const float*)d_in[2];
    const float* Wa     = (const float*)d_in[3];
    const float* ba     = (const float*)d_in[4];
    const float* Wb     = (const float*)d_in[5];
    const float* bb     = (const float*)d_in[6];
    const float* Wd     = (const float*)d_in[7];
    const float* bd     = (const float*)d_in[8];
    const float* gamma  = (const float*)d_in[9];
    const float* beta   = (const float*)d_in[10];
    float* out = (float*)d_out;

    const int smemA = (64 * XCP + 32 * XCP + 32 * WABP + 8 * 256) * sizeof(float); // 118784 B
    const int smemB = 111616;                                                      // bytes

    cudaFuncSetAttribute(attn_kernel, cudaFuncAttributeMaxDynamicSharedMemorySize, smemA);
    cudaFuncSetAttribute(out_kernel,  cudaFuncAttributeMaxDynamicSharedMemorySize, smemB);

    attn_kernel<<<N_ * S_, 256, smemA>>>(x, A_base, PA, Wa, ba, Wb, bb);
    out_kernel<<<dim3(T_ / 8, N_), 256, smemB>>>(x, Wd, bd, gamma, beta, out);
}

// round 11
// speedup vs baseline: 2.1463x; 1.2400x over previous
#include <cuda_runtime.h>
#include <cstdint>

#define N_  128
#define C_  64
#define T_  288
#define V_  16
#define S_  3
#define IC_ 16

// tiny scratch: attention matrices after softmax + A  [N, S, V, V]
__device__ float g_att[N_ * S_ * V_ * V_];

// ---- packed f32x2 helpers ------------------------------------------------
__device__ __forceinline__ unsigned long long pk2(float lo, float hi) {
    unsigned long long r;
    asm("mov.b64 %0, {%1, %2};" : "=l"(r) : "f"(lo), "f"(hi));
    return r;
}
__device__ __forceinline__ void ffma2(unsigned long long& acc,
                                      unsigned long long a,
                                      unsigned long long b) {
    asm("fma.rn.f32x2 %0, %1, %2, %0;" : "+l"(acc) : "l"(a), "l"(b));
}
__device__ __forceinline__ float2 upk(unsigned long long p) {
    float2 f;
    asm("mov.b64 {%0, %1}, %2;" : "=f"(f.x), "=f"(f.y) : "l"(p));
    return f;
}
__device__ __forceinline__ uint32_t f2tf32(float f) {
    uint32_t r;
    asm("cvt.rna.tf32.f32 %0, %1;" : "=r"(r) : "f"(f));
    return r;
}
__device__ __forceinline__ void mma_tf32(float& d0, float& d1, float& d2, float& d3,
                                         uint32_t a0, uint32_t a1, uint32_t a2, uint32_t a3,
                                         uint32_t b0, uint32_t b1) {
    asm volatile("mma.sync.aligned.m16n8k8.row.col.f32.tf32.tf32.f32 "
                 "{%0,%1,%2,%3}, {%4,%5,%6,%7}, {%8,%9}, {%0,%1,%2,%3};"
                 : "+f"(d0), "+f"(d1), "+f"(d2), "+f"(d3)
                 : "r"(a0), "r"(a1), "r"(a2), "r"(a3), "r"(b0), "r"(b1));
}

// ---------------------------------------------------------------------------
// Kernel A (tensor, 8-t chunks, 3 blocks/SM): per (n,s), per chunk:
//   phase1: F[32][128] = Wab[32][64] @ xchunk[64][128] (+bias), tf32 mma
//           warp = (fa|fb) x 32-col slab
//   phase2: gram += fa^T-slices @ fb over 128 k=(i,t); warp owns 16 k
//   tail: cross-warp reduce, /(IC*T), softmax over v, +A_base+PA -> g_att
// dyn smem: sXc [64][136] | sF [32][136] | sWab [32][72] | spart [8][256]
//           = 69632 B  -> 3 blocks/SM, grid 384 = single wave
// ---------------------------------------------------------------------------
#define XCPA 136
#define WABP 72
__global__ __launch_bounds__(256, 3) void attn_kernel(
    const float* __restrict__ x, const float* __restrict__ A_base,
    const float* __restrict__ PA, const float* __restrict__ Wa,
    const float* __restrict__ ba, const float* __restrict__ Wb,
    const float* __restrict__ bb)
{
    extern __shared__ float sm[];
    float* sXc   = sm;                          // [64][136]
    float* sF    = sm + 64 * XCPA;              // [32][136]
    float* sWab  = sF + 32 * XCPA;              // [32][72]
    float* spart = sWab + 32 * WABP;            // [8][256]

    __shared__ float sbias[32];
    __shared__ float satt[256];
    __shared__ float colmax[16], colinv[16];

    const int tid  = threadIdx.x;
    const int wid  = tid >> 5;
    const int lane = tid & 31;
    const int n = blockIdx.x / S_;
    const int s = blockIdx.x % S_;

    const int r    = lane >> 2;
    const int kq   = lane & 3;
    const int ncol = lane >> 2;

    // ---- Wab -> smem (fa rows 0-15, fb rows 16-31), raw fp32 bits
    {
        int i = tid >> 3, c8 = (tid & 7) * 8;
        const float* src = (i < 16)
            ? (Wa + (size_t)(s * 16 + i) * 64 + c8)
            : (Wb + (size_t)(s * 16 + (i - 16)) * 64 + c8);
        *reinterpret_cast<float4*>(sWab + i * WABP + c8)     = *reinterpret_cast<const float4*>(src);
        *reinterpret_cast<float4*>(sWab + i * WABP + c8 + 4) = *reinterpret_cast<const float4*>(src + 4);
    }
    if (tid < 16)      sbias[tid] = ba[s * 16 + tid];
    else if (tid < 32) sbias[tid] = bb[s * 16 + (tid - 16)];

    const float* xn = x + (size_t)n * (C_ * T_ * V_);

    // ---- chunk 0 x load: 64 rows x 128 floats
    for (int idx = tid; idx < 2048; idx += 256) {
        int c = idx >> 5, q = idx & 31;
        *reinterpret_cast<float4*>(sXc + c * XCPA + q * 4) =
            *reinterpret_cast<const float4*>(xn + (size_t)c * (T_ * V_) + q * 4);
    }
    __syncthreads();

    // phase1 roles: m-tile (fa/fb) and 32-col slab
    const int mt = wid & 1;
    const int n0 = (wid >> 1) * 32;
    const float b_r  = sbias[mt * 16 + r];
    const float b_r8 = sbias[mt * 16 + r + 8];
    const int row0 = mt * 16 + r;

    float gacc[2][4];
    gacc[0][0] = 0.f; gacc[0][1] = 0.f; gacc[0][2] = 0.f; gacc[0][3] = 0.f;
    gacc[1][0] = 0.f; gacc[1][1] = 0.f; gacc[1][2] = 0.f; gacc[1][3] = 0.f;

    const uint32_t* uWab = reinterpret_cast<const uint32_t*>(sWab);
    const uint32_t* uXc  = reinterpret_cast<const uint32_t*>(sXc);
    const uint32_t* uF   = reinterpret_cast<const uint32_t*>(sF);

    // phase2 roles: warp owns k = wid*16 .. +15 of 128 (k = i*8 + t)
    const int i2 = 2 * wid;            // ks selects i2 or i2+1

    for (int ch = 0; ch < 36; ch++) {
        // ---- phase1: F = Wab @ xchunk  (+bias)
        float acc[4][4];
        #pragma unroll
        for (int nt = 0; nt < 4; nt++) {
            acc[nt][0] = b_r; acc[nt][1] = b_r;
            acc[nt][2] = b_r8; acc[nt][3] = b_r8;
        }
        #pragma unroll
        for (int ks = 0; ks < 8; ks++) {
            const int k0 = ks * 8;
            uint32_t a0 = uWab[row0 * WABP + k0 + kq];
            uint32_t a1 = uWab[(row0 + 8) * WABP + k0 + kq];
            uint32_t a2 = uWab[row0 * WABP + k0 + 4 + kq];
            uint32_t a3 = uWab[(row0 + 8) * WABP + k0 + 4 + kq];
            const uint32_t* bp0 = uXc + (k0 + kq) * XCPA + n0 + ncol;
            const uint32_t* bp1 = uXc + (k0 + 4 + kq) * XCPA + n0 + ncol;
            #pragma unroll
            for (int nt = 0; nt < 4; nt++) {
                mma_tf32(acc[nt][0], acc[nt][1], acc[nt][2], acc[nt][3],
                         a0, a1, a2, a3, bp0[nt * 8], bp1[nt * 8]);
            }
        }
        #pragma unroll
        for (int nt = 0; nt < 4; nt++) {
            const int col = n0 + nt * 8 + 2 * kq;
            *reinterpret_cast<float2*>(sF + row0 * XCPA + col) =
                make_float2(acc[nt][0], acc[nt][1]);
            *reinterpret_cast<float2*>(sF + (row0 + 8) * XCPA + col) =
                make_float2(acc[nt][2], acc[nt][3]);
        }
        __syncthreads();   // F ready; sXc fully consumed

        // ---- x load for next chunk (overlaps phase2)
        if (ch < 35) {
            const float* src = xn + (ch + 1) * 128;
            for (int idx = tid; idx < 2048; idx += 256) {
                int c = idx >> 5, q = idx & 31;
                *reinterpret_cast<float4*>(sXc + c * XCPA + q * 4) =
                    *reinterpret_cast<const float4*>(src + (size_t)c * (T_ * V_) + q * 4);
            }
        }

        // ---- phase2: gram += fa^T @ fb over this chunk's 128 k
        #pragma unroll
        for (int ks = 0; ks < 2; ks++) {
            const int i = i2 + ks;
            uint32_t a0 = uF[i * XCPA + kq * 16 + r];
            uint32_t a1 = uF[i * XCPA + kq * 16 + r + 8];
            uint32_t a2 = uF[i * XCPA + (kq + 4) * 16 + r];
            uint32_t a3 = uF[i * XCPA + (kq + 4) * 16 + r + 8];
            #pragma unroll
            for (int nt = 0; nt < 2; nt++) {
                uint32_t b0 = uF[(16 + i) * XCPA + kq * 16 + nt * 8 + ncol];
                uint32_t b1 = uF[(16 + i) * XCPA + (kq + 4) * 16 + nt * 8 + ncol];
                mma_tf32(gacc[nt][0], gacc[nt][1], gacc[nt][2], gacc[nt][3],
                         a0, a1, a2, a3, b0, b1);
            }
        }
        __syncthreads();   // phase2 done reading sF; sXc(ch+1) ready
    }

    // ---- cross-warp reduce of gram partials
    #pragma unroll
    for (int nt = 0; nt < 2; nt++) {
        float* p = spart + wid * 256 + nt * 8 + 2 * kq;
        p[r * 16]           = gacc[nt][0];
        p[r * 16 + 1]       = gacc[nt][1];
        p[(r + 8) * 16]     = gacc[nt][2];
        p[(r + 8) * 16 + 1] = gacc[nt][3];
    }
    __syncthreads();

    float attacc = 0.f;
    #pragma unroll
    for (int w8 = 0; w8 < 8; w8++) attacc += spart[w8 * 256 + tid];
    attacc *= (1.0f / (float)(IC_ * T_));
    satt[tid] = attacc;
    __syncthreads();

    const int v = tid >> 4;
    const int w = tid & 15;
    if (tid < 16) {
        float m = -1e30f;
        #pragma unroll
        for (int vv = 0; vv < 16; vv++) m = fmaxf(m, satt[vv * 16 + tid]);
        float ssum = 0.f;
        #pragma unroll
        for (int vv = 0; vv < 16; vv++) ssum += __expf(satt[vv * 16 + tid] - m);
        colmax[tid] = m;
        colinv[tid] = 1.0f / ssum;
    }
    __syncthreads();

    float rr = __expf(attacc - colmax[w]) * colinv[w]
             + A_base[(s * 16 + v) * 16 + w] + PA[(s * 16 + v) * 16 + w];
    g_att[((n * 3 + s) * 16 + v) * 16 + w] = rr;
}

// ---------------------------------------------------------------------------
// Kernel B: unchanged from R8/R9 (passing, ~275us)
// ---------------------------------------------------------------------------
#define ZP 74
#define WP 72
#define XP 132
__global__ __launch_bounds__(256, 2) void out_kernel(
    const float* __restrict__ x, const float* __restrict__ Wd,
    const float* __restrict__ bd, const float* __restrict__ gamma,
    const float* __restrict__ beta, float* __restrict__ out)
{
    extern __shared__ char smem[];
    uint32_t* sZ  = (uint32_t*)(smem);                 // [128][ZP] tf32
    float*    sO  = (float*)(smem);                    // epilogue reuse [64][XP]
    uint32_t* sW0 = (uint32_t*)(smem + 37888);         // [64][WP] tf32
    uint32_t* sW1 = (uint32_t*)(smem + 56320);
    float*    sX  = (float*)(smem + 74752);            // [64][XP]
    float*    sAtt= (float*)(smem + 108544);           // [3][16][16]

    __shared__ float sBN[3 * 64];

    const int tid  = threadIdx.x;
    const int wid  = tid >> 5;
    const int lane = tid & 31;
    const int n  = blockIdx.y;
    const int t0 = blockIdx.x * 8;

    for (int idx = tid; idx < 768; idx += 256)
        sAtt[idx] = g_att[n * 768 + idx];
    for (int idx = tid; idx < 64 * 32; idx += 256) {
        int c = idx >> 5, q = idx & 31;
        reinterpret_cast<float4*>(sX + c * XP)[q] =
            reinterpret_cast<const float4*>(x + (size_t)(n * 64 + c) * (T_ * V_) + t0 * V_)[q];
    }
    #pragma unroll
    for (int q = 0; q < 4; q++) {
        int i4 = tid * 4 + q;
        int o = i4 >> 4, c4 = i4 & 15;
        float4 wv = reinterpret_cast<const float4*>(Wd)[i4];
        sW0[(c4 * 4 + 0) * WP + o] = f2tf32(wv.x);
        sW0[(c4 * 4 + 1) * WP + o] = f2tf32(wv.y);
        sW0[(c4 * 4 + 2) * WP + o] = f2tf32(wv.z);
        sW0[(c4 * 4 + 3) * WP + o] = f2tf32(wv.w);
    }
    if (tid < 64) {
        int o = tid;
        sBN[o]       = bd[o] + bd[64 + o] + bd[128 + o];
        sBN[64 + o]  = gamma[o] * rsqrtf(1.0f + 1e-5f);
        sBN[128 + o] = beta[o];
    }
    __syncthreads();

    const int c1 = tid >> 2;
    const int wg = tid & 3;

    const int m0   = wid * 16;
    const int rA0  = m0 + (lane >> 2);
    const int kq   = lane & 3;
    const int ncol = lane >> 2;

    float acc[8][4];
    #pragma unroll
    for (int nf = 0; nf < 8; nf++) {
        acc[nf][0] = 0.f; acc[nf][1] = 0.f; acc[nf][2] = 0.f; acc[nf][3] = 0.f;
    }

    #pragma unroll
    for (int s = 0; s < S_; s++) {
        uint32_t* sWcur = (s & 1) ? sW1 : sW0;

        ulonglong2 ar[16];
        #pragma unroll
        for (int v = 0; v < 16; v++)
            ar[v] = *reinterpret_cast<const ulonglong2*>(sAtt + s * 256 + v * 16 + wg * 4);

        #pragma unroll
        for (int tt = 0; tt < 8; tt++) {
            const float4* xp = reinterpret_cast<const float4*>(sX + c1 * XP + tt * 16);
            float xr[16];
            #pragma unroll
            for (int q = 0; q < 4; q++) {
                float4 xx = xp[q];
                xr[q * 4 + 0] = xx.x; xr[q * 4 + 1] = xx.y;
                xr[q * 4 + 2] = xx.z; xr[q * 4 + 3] = xx.w;
            }
            unsigned long long a0 = 0ull, a1 = 0ull;
            #pragma unroll
            for (int v = 0; v < 16; v++) {
                unsigned long long xd = pk2(xr[v], xr[v]);
                ffma2(a0, xd, ar[v].x);
                ffma2(a1, xd, ar[v].y);
            }
            float2 f0 = upk(a0), f1 = upk(a1);
            const int twb = tt * 16 + wg * 4;
            sZ[(twb + 0) * ZP + c1] = f2tf32(f0.x);
            sZ[(twb + 1) * ZP + c1] = f2tf32(f0.y);
            sZ[(twb + 2) * ZP + c1] = f2tf32(f1.x);
            sZ[(twb + 3) * ZP + c1] = f2tf32(f1.y);
        }

        if (s < 2) {
            uint32_t* sWn = ((s + 1) & 1) ? sW1 : sW0;
            const float4* src = reinterpret_cast<const float4*>(Wd + (size_t)(s + 1) * 4096);
            #pragma unroll
            for (int q = 0; q < 4; q++) {
                int i4 = tid * 4 + q;
                int o = i4 >> 4, c4 = i4 & 15;
                float4 wv = src[i4];
                sWn[(c4 * 4 + 0) * WP + o] = f2tf32(wv.x);
                sWn[(c4 * 4 + 1) * WP + o] = f2tf32(wv.y);
                sWn[(c4 * 4 + 2) * WP + o] = f2tf32(wv.z);
                sWn[(c4 * 4 + 3) * WP + o] = f2tf32(wv.w);
            }
        }
        __syncthreads();

        #pragma unroll
        for (int ks = 0; ks < 8; ks++) {
            const int k0 = ks * 8;
            uint32_t a0 = sZ[rA0 * ZP + k0 + kq];
            uint32_t a1 = sZ[(rA0 + 8) * ZP + k0 + kq];
            uint32_t a2 = sZ[rA0 * ZP + k0 + 4 + kq];
            uint32_t a3 = sZ[(rA0 + 8) * ZP + k0 + 4 + kq];
            const uint32_t* bp0 = sWcur + (k0 + kq) * WP + ncol;
            const uint32_t* bp1 = sWcur + (k0 + 4 + kq) * WP + ncol;
            #pragma unroll
            for (int nf = 0; nf < 8; nf++) {
                uint32_t b0 = bp0[nf * 8];
                uint32_t b1 = bp1[nf * 8];
                mma_tf32(acc[nf][0], acc[nf][1], acc[nf][2], acc[nf][3],
                         a0, a1, a2, a3, b0, b1);
            }
        }
        __syncthreads();
    }

    {
        const int r0 = m0 + (lane >> 2);
        #pragma unroll
        for (int nf = 0; nf < 8; nf++) {
            int o0 = nf * 8 + 2 * (lane & 3);
            float s0 = sBN[64 + o0],     b0v = sBN[o0],     z0 = sBN[128 + o0];
            float s1 = sBN[64 + o0 + 1], b1v = sBN[o0 + 1], z1 = sBN[128 + o0 + 1];
            sO[o0 * XP + r0]           = (acc[nf][0] + b0v) * s0 + z0;
            sO[(o0 + 1) * XP + r0]     = (acc[nf][1] + b1v) * s1 + z1;
            sO[o0 * XP + r0 + 8]       = (acc[nf][2] + b0v) * s0 + z0;
            sO[(o0 + 1) * XP + r0 + 8] = (acc[nf][3] + b1v) * s1 + z1;
        }
    }
    __syncthreads();

    for (int idx = tid; idx < 64 * 32; idx += 256) {
        int c = idx >> 5, q = idx & 31;
        float4 yv = reinterpret_cast<const float4*>(sO + c * XP)[q];
        float4 xv = reinterpret_cast<const float4*>(sX + c * XP)[q];
        yv.x += xv.x; yv.y += xv.y; yv.z += xv.z; yv.w += xv.w;
        reinterpret_cast<float4*>(out + (size_t)(n * 64 + c) * (T_ * V_) + t0 * V_)[q] = yv;
    }
}

extern "C" void kernel_launch(void* const* d_in, const int* in_sizes, int n_in,
                              void* d_out, int out_size)
{
    const float* x      = (const float*)d_in[0];
    const float* A_base = (const float*)d_in[1];
    const float* PA     = (const float*)d_in[2];
    const float* Wa     = (const float*)d_in[3];
    const float* ba     = (const float*)d_in[4];
    const float* Wb     = (const float*)d_in[5];
    const float* bb     = (const float*)d_in[6];
    const float* Wd     = (const float*)d_in[7];
    const float* bd     = (const float*)d_in[8];
    const float* gamma  = (const float*)d_in[9];
    const float* beta   = (const float*)d_in[10];
    float* out = (float*)d_out;

    const int smemA = (64 * XCPA + 32 * XCPA + 32 * WABP + 8 * 256) * sizeof(float); // 69632 B
    const int smemB = 111616;                                                        // bytes

    cudaFuncSetAttribute(attn_kernel, cudaFuncAttributeMaxDynamicSharedMemorySize, smemA);
    cudaFuncSetAttribute(out_kernel,  cudaFuncAttributeMaxDynamicSharedMemorySize, smemB);

    attn_kernel<<<N_ * S_, 256, smemA>>>(x, A_base, PA, Wa, ba, Wb, bb);
    out_kernel<<<dim3(T_ / 8, N_), 256, smemB>>>(x, Wd, bd, gamma, beta, out);
}